// round 1
// baseline (speedup 1.0000x reference)
#include <cuda_runtime.h>

#define NN 50000
#define NG 64
#define MAXH 512
#define BN_EPS 1e-5f

// ---------------- scratch (device globals; no allocation allowed) -------------
__device__ __align__(16) float g_h[(size_t)NN * MAXH];     // GEMM output
__device__ __align__(16) float g_agg[(size_t)NN * MAXH];   // conv output / layer activations
__device__ float g_deg[NN];
__device__ float g_dinv[NN];
__device__ float g_sum[MAXH];
__device__ float g_sqs[MAXH];
__device__ float g_pool[NG * 128];
__device__ float g_cnt[NG];

// ---------------- small utility kernels --------------------------------------
__global__ void k_fill(float* p, int n, float v) {
    int i = blockIdx.x * blockDim.x + threadIdx.x;
    if (i < n) p[i] = v;
}

__global__ void k_deg_edges(const int* __restrict__ col, float* deg, int E) {
    int i = blockIdx.x * blockDim.x + threadIdx.x;
    if (i < E) atomicAdd(&deg[col[i]], 1.0f);
}

__global__ void k_dinv(const float* __restrict__ deg, float* dinv, int n) {
    int i = blockIdx.x * blockDim.x + threadIdx.x;
    if (i < n) {
        float d = deg[i];
        dinv[i] = d > 0.f ? rsqrtf(d) : 0.f;
    }
}

// ---------------- tiled fp32 GEMM: C[M,N] = A[M,K] * B[K,N] ------------------
#define BM 64
#define BNT 64
#define BK 16
__global__ void k_gemm(const float* __restrict__ A, const float* __restrict__ B,
                       float* __restrict__ C, int M, int K, int N) {
    __shared__ float As[BK][BM];
    __shared__ float Bs[BK][BNT];

    int tx = threadIdx.x & 15;        // 0..15  -> 4 cols each
    int ty = threadIdx.x >> 4;        // 0..15  -> 4 rows each
    int rowBase = blockIdx.y * BM;
    int colBase = blockIdx.x * BNT;

    float acc[4][4] = {};

    for (int k0 = 0; k0 < K; k0 += BK) {
        // load A tile (64 x 16)
        for (int l = threadIdx.x; l < BM * BK; l += 256) {
            int r = l >> 4, c = l & 15;
            int gr = rowBase + r;
            As[c][r] = (gr < M) ? A[(size_t)gr * K + k0 + c] : 0.f;
        }
        // load B tile (16 x 64)
        for (int l = threadIdx.x; l < BK * BNT; l += 256) {
            int r = l >> 6, c = l & 63;
            Bs[r][c] = B[(size_t)(k0 + r) * N + colBase + c];
        }
        __syncthreads();

#pragma unroll
        for (int k = 0; k < BK; k++) {
            float4 a = *(const float4*)&As[k][ty * 4];
            float4 b = *(const float4*)&Bs[k][tx * 4];
            float av[4] = {a.x, a.y, a.z, a.w};
            float bv[4] = {b.x, b.y, b.z, b.w};
#pragma unroll
            for (int i = 0; i < 4; i++)
#pragma unroll
                for (int j = 0; j < 4; j++)
                    acc[i][j] += av[i] * bv[j];
        }
        __syncthreads();
    }

#pragma unroll
    for (int i = 0; i < 4; i++) {
        int gr = rowBase + ty * 4 + i;
        if (gr < M) {
            float4 v = make_float4(acc[i][0], acc[i][1], acc[i][2], acc[i][3]);
            *(float4*)&C[(size_t)gr * N + colBase + tx * 4] = v;
        }
    }
}

// ---------------- agg init: self-loop + bias ----------------------------------
// agg[n][c] = h[n][c]*dinv[n]^2 + b[c]
__global__ void k_selfbias(const float* __restrict__ h, float* __restrict__ agg,
                           const float* __restrict__ dinv, const float* __restrict__ b,
                           int total, int hshift, int hmask) {
    int i = blockIdx.x * blockDim.x + threadIdx.x;
    if (i >= total) return;
    int node = i >> hshift;
    int c = i & hmask;
    float di = dinv[node];
    agg[i] = h[i] * di * di + b[c];
}

// ---------------- edge scatter: agg[col] += h[row] * dinv[row]*dinv[col] ------
__global__ void k_scatter(const float* __restrict__ h, const int* __restrict__ row,
                          const int* __restrict__ col, const float* __restrict__ dinv,
                          float* __restrict__ agg, int items, int cshift, int H) {
    int i = blockIdx.x * blockDim.x + threadIdx.x;
    if (i >= items) return;
    int e = i >> cshift;
    int c = (i - (e << cshift)) << 2;
    int r = __ldg(&row[e]);
    int d = __ldg(&col[e]);
    float nrm = __ldg(&dinv[r]) * __ldg(&dinv[d]);
    float4 v = __ldg((const float4*)(h + (size_t)r * H + c));
    float wx = v.x * nrm, wy = v.y * nrm, wz = v.z * nrm, ww = v.w * nrm;
    float* dst = agg + (size_t)d * H + c;
    asm volatile("red.global.add.v4.f32 [%0], {%1,%2,%3,%4};"
                 :: "l"(dst), "f"(wx), "f"(wy), "f"(wz), "f"(ww) : "memory");
}

// ---------------- BN statistics (sum + sumsq per feature) ---------------------
__global__ void k_zero2(float* a, float* b, int n) {
    int i = blockIdx.x * blockDim.x + threadIdx.x;
    if (i < n) { a[i] = 0.f; b[i] = 0.f; }
}

__global__ void k_stats(const float* __restrict__ x, int total, int H,
                        float* __restrict__ sum, float* __restrict__ sqs) {
    extern __shared__ float sh[];
    float* ssum = sh;
    float* ssq = sh + H;
    for (int c = threadIdx.x; c < H; c += blockDim.x) { ssum[c] = 0.f; ssq[c] = 0.f; }
    __syncthreads();
    int hmask = H - 1;
    for (int i = blockIdx.x * blockDim.x + threadIdx.x; i < total;
         i += gridDim.x * blockDim.x) {
        float v = x[i];
        int c = i & hmask;
        atomicAdd(&ssum[c], v);
        atomicAdd(&ssq[c], v * v);
    }
    __syncthreads();
    for (int c = threadIdx.x; c < H; c += blockDim.x) {
        atomicAdd(&sum[c], ssum[c]);
        atomicAdd(&sqs[c], ssq[c]);
    }
}

// ---------------- BN normalize + ReLU (in place) ------------------------------
__global__ void k_bnrelu(float* __restrict__ x, int total, int hmask,
                         const float* __restrict__ sum, const float* __restrict__ sqs,
                         const float* __restrict__ g, const float* __restrict__ be) {
    int i = blockIdx.x * blockDim.x + threadIdx.x;
    if (i >= total) return;
    int c = i & hmask;
    const float invN = 1.0f / (float)NN;
    float mean = sum[c] * invN;
    float var = sqs[c] * invN - mean * mean;
    float s = rsqrtf(var + BN_EPS) * g[c];
    float v = (x[i] - mean) * s + be[c];
    x[i] = v > 0.f ? v : 0.f;
}

// ---------------- pooling + output head --------------------------------------
__global__ void k_cnt(const int* __restrict__ batch, float* cnt, int n) {
    int i = blockIdx.x * blockDim.x + threadIdx.x;
    if (i < n) atomicAdd(&cnt[batch[i]], 1.0f);
}

__global__ void k_poolsum(const float* __restrict__ h, const int* __restrict__ batch,
                          float* __restrict__ pool, int total) {
    int i = blockIdx.x * blockDim.x + threadIdx.x;
    if (i >= total) return;
    int node = i >> 7;          // H3 = 128
    int c = i & 127;
    atomicAdd(&pool[batch[node] * 128 + c], h[i]);
}

__global__ void k_final(const float* __restrict__ pool, const float* __restrict__ cnt,
                        const float* __restrict__ Wo, const float* __restrict__ bo,
                        float* __restrict__ out) {
    int t = blockIdx.x * blockDim.x + threadIdx.x;
    if (t >= NG * 10) return;
    int gph = t / 10, o = t % 10;
    float inv = 1.0f / fmaxf(cnt[gph], 1.0f);
    float acc = bo[o];
#pragma unroll 8
    for (int k = 0; k < 128; k++)
        acc += pool[gph * 128 + k] * inv * Wo[k * 10 + o];
    out[t] = acc;
}

// ---------------- host orchestration ------------------------------------------
static inline int ilog2(int v) { int s = 0; while ((1 << s) < v) s++; return s; }

static void run_layer(const float* in, int K, int H, const float* W, const float* b,
                      const float* g, const float* be, const int* row, const int* col,
                      int E, float* h, float* agg, float* dinv, float* sum, float* sqs) {
    dim3 grid(H / BNT, (NN + BM - 1) / BM);
    k_gemm<<<grid, 256>>>(in, W, h, NN, K, H);

    int total = NN * H;
    int hshift = ilog2(H);
    k_selfbias<<<(total + 255) / 256, 256>>>(h, agg, dinv, b, total, hshift, H - 1);

    int cshift = ilog2(H / 4);
    int items = E * (H / 4);
    k_scatter<<<(items + 255) / 256, 256>>>(h, row, col, dinv, agg, items, cshift, H);

    k_zero2<<<(H + 127) / 128, 128>>>(sum, sqs, H);
    k_stats<<<2048, 256, 2 * H * sizeof(float)>>>(agg, total, H, sum, sqs);
    k_bnrelu<<<(total + 255) / 256, 256>>>(agg, total, H - 1, sum, sqs, g, be);
}

extern "C" void kernel_launch(void* const* d_in, const int* in_sizes, int n_in,
                              void* d_out, int out_size) {
    const float* x     = (const float*)d_in[0];
    const int*   ei    = (const int*)d_in[1];
    const int*   batch = (const int*)d_in[2];
    const float* W1 = (const float*)d_in[3];  const float* b1 = (const float*)d_in[4];
    const float* g1 = (const float*)d_in[5];  const float* be1 = (const float*)d_in[6];
    const float* W2 = (const float*)d_in[7];  const float* b2 = (const float*)d_in[8];
    const float* g2 = (const float*)d_in[9];  const float* be2 = (const float*)d_in[10];
    const float* W3 = (const float*)d_in[11]; const float* b3 = (const float*)d_in[12];
    const float* g3 = (const float*)d_in[13]; const float* be3 = (const float*)d_in[14];
    const float* Wo = (const float*)d_in[15]; const float* bo = (const float*)d_in[16];
    float* out = (float*)d_out;

    int E = in_sizes[1] / 2;
    const int* row = ei;
    const int* col = ei + E;

    float *h, *agg, *deg, *dinv, *sum, *sqs, *pool, *cnt;
    cudaGetSymbolAddress((void**)&h, g_h);
    cudaGetSymbolAddress((void**)&agg, g_agg);
    cudaGetSymbolAddress((void**)&deg, g_deg);
    cudaGetSymbolAddress((void**)&dinv, g_dinv);
    cudaGetSymbolAddress((void**)&sum, g_sum);
    cudaGetSymbolAddress((void**)&sqs, g_sqs);
    cudaGetSymbolAddress((void**)&pool, g_pool);
    cudaGetSymbolAddress((void**)&cnt, g_cnt);

    // degree (with self loops) -> dinv
    k_fill<<<(NN + 255) / 256, 256>>>(deg, NN, 1.0f);
    k_deg_edges<<<(E + 255) / 256, 256>>>(col, deg, E);
    k_dinv<<<(NN + 255) / 256, 256>>>(deg, dinv, NN);

    // 3 GCN layers (activations live in g_agg between layers)
    run_layer(x,   128, 512, W1, b1, g1, be1, row, col, E, h, agg, dinv, sum, sqs);
    run_layer(agg, 512, 256, W2, b2, g2, be2, row, col, E, h, agg, dinv, sum, sqs);
    run_layer(agg, 256, 128, W3, b3, g3, be3, row, col, E, h, agg, dinv, sum, sqs);

    // global mean pool + head
    k_fill<<<(NG * 128 + 255) / 256, 256>>>(pool, NG * 128, 0.0f);
    k_fill<<<1, 128>>>(cnt, NG, 0.0f);
    k_cnt<<<(NN + 255) / 256, 256>>>(batch, cnt, NN);
    k_poolsum<<<(NN * 128 + 255) / 256, 256>>>(agg, batch, pool, NN * 128);
    k_final<<<(NG * 10 + 127) / 128, 128>>>(pool, cnt, Wo, bo, out);
}

// round 2
// speedup vs baseline: 1.3544x; 1.3544x over previous
#include <cuda_runtime.h>

#define NN 50000
#define NG 64
#define MAXH 512
#define BN_EPS 1e-5f

// ---------------- scratch (device globals; no allocation allowed) -------------
__device__ __align__(16) float g_h[(size_t)NN * MAXH];     // GEMM output (pre-norm h)
__device__ __align__(16) float g_agg[(size_t)NN * MAXH];   // conv output / activations
__device__ float g_deg[NN];
__device__ float g_dinv[NN];
__device__ float g_sum[MAXH];
__device__ float g_sqs[MAXH];
__device__ float g_pool[NG * 128];
__device__ float g_cnt[NG];

// ---------------- small utility kernels --------------------------------------
__global__ void k_fill(float* p, int n, float v) {
    int i = blockIdx.x * blockDim.x + threadIdx.x;
    if (i < n) p[i] = v;
}

__global__ void k_deg_edges(const int* __restrict__ col, float* deg, int E) {
    int i = blockIdx.x * blockDim.x + threadIdx.x;
    if (i < E) atomicAdd(&deg[col[i]], 1.0f);
}

__global__ void k_dinv(const float* __restrict__ deg, float* dinv, int n) {
    int i = blockIdx.x * blockDim.x + threadIdx.x;
    if (i < n) {
        float d = deg[i];
        dinv[i] = d > 0.f ? rsqrtf(d) : 0.f;
    }
}

// ---------------- 128x128x16 double-buffered SGEMM, 8x8 per thread -----------
// C = A[M,K] @ B[K,N].  Fused epilogue: H = C ; AGG = C*dinv[row]^2 + bias[col]
#define TBM 128
#define TBN 128
#define TBK 16
#define ASTRIDE 132   // padded to kill 4-way bank conflicts on As stores

__global__ __launch_bounds__(256, 2)
void k_gemm_fused(const float* __restrict__ A, const float* __restrict__ B,
                  float* __restrict__ H, float* __restrict__ AGG,
                  const float* __restrict__ dinv, const float* __restrict__ bias,
                  int M, int K, int N) {
    __shared__ float As[2][TBK][ASTRIDE];
    __shared__ float Bs[2][TBK][TBN];

    const int tid = threadIdx.x;
    const int rowBase = blockIdx.y * TBM;
    const int colBase = blockIdx.x * TBN;

    // A-tile loader mapping: 128 rows x 16 cols, 2 float4 per thread
    const int ar = tid >> 2;           // 0..63 (+64 for second)
    const int ac = (tid & 3) << 2;     // 0,4,8,12
    // B-tile loader mapping: 16 rows x 128 cols, 2 float4 per thread
    const int br = tid >> 5;           // 0..7 (+8 for second)
    const int bc = (tid & 31) << 2;    // 0..124

    // compute mapping
    const int tx = tid & 15;           // col group
    const int ty = tid >> 4;           // row group

    float acc[8][8] = {};

    const int nk = K / TBK;

    // ---- preload tile 0 ----
    {
#pragma unroll
        for (int s = 0; s < 2; s++) {
            int r = ar + s * 64;
            int gr = rowBase + r;
            float4 v = (gr < M) ? *(const float4*)&A[(size_t)gr * K + ac]
                                : make_float4(0.f, 0.f, 0.f, 0.f);
            As[0][ac + 0][r] = v.x; As[0][ac + 1][r] = v.y;
            As[0][ac + 2][r] = v.z; As[0][ac + 3][r] = v.w;
        }
#pragma unroll
        for (int s = 0; s < 2; s++) {
            int r = br + s * 8;
            *(float4*)&Bs[0][r][bc] = *(const float4*)&B[(size_t)r * N + colBase + bc];
        }
    }
    __syncthreads();

    for (int kt = 0; kt < nk; kt++) {
        int buf = kt & 1;
        // prefetch next tile into other buffer
        if (kt + 1 < nk) {
            int k0 = (kt + 1) * TBK;
#pragma unroll
            for (int s = 0; s < 2; s++) {
                int r = ar + s * 64;
                int gr = rowBase + r;
                float4 v = (gr < M) ? *(const float4*)&A[(size_t)gr * K + k0 + ac]
                                    : make_float4(0.f, 0.f, 0.f, 0.f);
                As[buf ^ 1][ac + 0][r] = v.x; As[buf ^ 1][ac + 1][r] = v.y;
                As[buf ^ 1][ac + 2][r] = v.z; As[buf ^ 1][ac + 3][r] = v.w;
            }
#pragma unroll
            for (int s = 0; s < 2; s++) {
                int r = br + s * 8;
                *(float4*)&Bs[buf ^ 1][r][bc] =
                    *(const float4*)&B[(size_t)(k0 + r) * N + colBase + bc];
            }
        }

#pragma unroll
        for (int k = 0; k < TBK; k++) {
            float a[8], b[8];
            *(float4*)&a[0] = *(const float4*)&As[buf][k][ty * 4];
            *(float4*)&a[4] = *(const float4*)&As[buf][k][ty * 4 + 64];
            *(float4*)&b[0] = *(const float4*)&Bs[buf][k][tx * 4];
            *(float4*)&b[4] = *(const float4*)&Bs[buf][k][tx * 4 + 64];
#pragma unroll
            for (int i = 0; i < 8; i++)
#pragma unroll
                for (int j = 0; j < 8; j++)
                    acc[i][j] += a[i] * b[j];
        }
        __syncthreads();
    }

    // ---- fused epilogue: H = acc ; AGG = acc*dinv^2 + bias ----
    float4 bl0 = *(const float4*)&bias[colBase + tx * 4];
    float4 bl1 = *(const float4*)&bias[colBase + tx * 4 + 64];
    float blo[8] = {bl0.x, bl0.y, bl0.z, bl0.w, bl1.x, bl1.y, bl1.z, bl1.w};

#pragma unroll
    for (int i = 0; i < 8; i++) {
        int r = (i < 4) ? (ty * 4 + i) : (ty * 4 + 64 + i - 4);
        int gr = rowBase + r;
        if (gr >= M) continue;
        float di = dinv[gr];
        float d2 = di * di;
        size_t base = (size_t)gr * N;
#pragma unroll
        for (int jj = 0; jj < 2; jj++) {
            int c = colBase + tx * 4 + jj * 64;
            float4 hv = make_float4(acc[i][jj * 4 + 0], acc[i][jj * 4 + 1],
                                    acc[i][jj * 4 + 2], acc[i][jj * 4 + 3]);
            *(float4*)&H[base + c] = hv;
            float4 av = make_float4(hv.x * d2 + blo[jj * 4 + 0],
                                    hv.y * d2 + blo[jj * 4 + 1],
                                    hv.z * d2 + blo[jj * 4 + 2],
                                    hv.w * d2 + blo[jj * 4 + 3]);
            *(float4*)&AGG[base + c] = av;
        }
    }
}

// ---------------- edge scatter: agg[col] += h[row] * dinv[row]*dinv[col] ------
__global__ void k_scatter(const float* __restrict__ h, const int* __restrict__ row,
                          const int* __restrict__ col, const float* __restrict__ dinv,
                          float* __restrict__ agg, int items, int cshift, int H) {
    int i = blockIdx.x * blockDim.x + threadIdx.x;
    if (i >= items) return;
    int e = i >> cshift;
    int c = (i - (e << cshift)) << 2;
    int r = __ldg(&row[e]);
    int d = __ldg(&col[e]);
    float nrm = __ldg(&dinv[r]) * __ldg(&dinv[d]);
    float4 v = __ldg((const float4*)(h + (size_t)r * H + c));
    float wx = v.x * nrm, wy = v.y * nrm, wz = v.z * nrm, ww = v.w * nrm;
    float* dst = agg + (size_t)d * H + c;
    asm volatile("red.global.add.v4.f32 [%0], {%1,%2,%3,%4};"
                 :: "l"(dst), "f"(wx), "f"(wy), "f"(wz), "f"(ww) : "memory");
}

// ---------------- BN statistics (sum + sumsq per feature) ---------------------
__global__ void k_zero2(float* a, float* b, int n) {
    int i = blockIdx.x * blockDim.x + threadIdx.x;
    if (i < n) { a[i] = 0.f; b[i] = 0.f; }
}

__global__ void k_stats(const float* __restrict__ x, int total, int H,
                        float* __restrict__ sum, float* __restrict__ sqs) {
    extern __shared__ float sh[];
    float* ssum = sh;
    float* ssq = sh + H;
    for (int c = threadIdx.x; c < H; c += blockDim.x) { ssum[c] = 0.f; ssq[c] = 0.f; }
    __syncthreads();
    int hmask = H - 1;
    for (int i = blockIdx.x * blockDim.x + threadIdx.x; i < total;
         i += gridDim.x * blockDim.x) {
        float v = x[i];
        int c = i & hmask;
        atomicAdd(&ssum[c], v);
        atomicAdd(&ssq[c], v * v);
    }
    __syncthreads();
    for (int c = threadIdx.x; c < H; c += blockDim.x) {
        atomicAdd(&sum[c], ssum[c]);
        atomicAdd(&sqs[c], ssq[c]);
    }
}

// ---------------- BN normalize + ReLU (in place) ------------------------------
__global__ void k_bnrelu(float* __restrict__ x, int total, int hmask,
                         const float* __restrict__ sum, const float* __restrict__ sqs,
                         const float* __restrict__ g, const float* __restrict__ be) {
    int i = blockIdx.x * blockDim.x + threadIdx.x;
    if (i >= total) return;
    int c = i & hmask;
    const float invN = 1.0f / (float)NN;
    float mean = sum[c] * invN;
    float var = sqs[c] * invN - mean * mean;
    float s = rsqrtf(var + BN_EPS) * g[c];
    float v = (x[i] - mean) * s + be[c];
    x[i] = v > 0.f ? v : 0.f;
}

// ---------------- pooling + output head --------------------------------------
__global__ void k_cnt(const int* __restrict__ batch, float* cnt, int n) {
    int i = blockIdx.x * blockDim.x + threadIdx.x;
    if (i < n) atomicAdd(&cnt[batch[i]], 1.0f);
}

__global__ void k_poolsum(const float* __restrict__ h, const int* __restrict__ batch,
                          float* __restrict__ pool, int total) {
    int i = blockIdx.x * blockDim.x + threadIdx.x;
    if (i >= total) return;
    int node = i >> 7;          // H3 = 128
    int c = i & 127;
    atomicAdd(&pool[batch[node] * 128 + c], h[i]);
}

__global__ void k_final(const float* __restrict__ pool, const float* __restrict__ cnt,
                        const float* __restrict__ Wo, const float* __restrict__ bo,
                        float* __restrict__ out) {
    int t = blockIdx.x * blockDim.x + threadIdx.x;
    if (t >= NG * 10) return;
    int gph = t / 10, o = t % 10;
    float inv = 1.0f / fmaxf(cnt[gph], 1.0f);
    float acc = bo[o];
#pragma unroll 8
    for (int k = 0; k < 128; k++)
        acc += pool[gph * 128 + k] * inv * Wo[k * 10 + o];
    out[t] = acc;
}

// ---------------- host orchestration ------------------------------------------
static inline int ilog2(int v) { int s = 0; while ((1 << s) < v) s++; return s; }

static void run_layer(const float* in, int K, int H, const float* W, const float* b,
                      const float* g, const float* be, const int* row, const int* col,
                      int E, float* h, float* agg, float* dinv, float* sum, float* sqs) {
    dim3 grid(H / TBN, (NN + TBM - 1) / TBM);
    k_gemm_fused<<<grid, 256>>>(in, W, h, agg, dinv, b, NN, K, H);

    int total = NN * H;
    int cshift = ilog2(H / 4);
    int items = E * (H / 4);
    k_scatter<<<(items + 255) / 256, 256>>>(h, row, col, dinv, agg, items, cshift, H);

    k_zero2<<<(H + 127) / 128, 128>>>(sum, sqs, H);
    k_stats<<<2048, 256, 2 * H * sizeof(float)>>>(agg, total, H, sum, sqs);
    k_bnrelu<<<(total + 255) / 256, 256>>>(agg, total, H - 1, sum, sqs, g, be);
}

extern "C" void kernel_launch(void* const* d_in, const int* in_sizes, int n_in,
                              void* d_out, int out_size) {
    const float* x     = (const float*)d_in[0];
    const int*   ei    = (const int*)d_in[1];
    const int*   batch = (const int*)d_in[2];
    const float* W1 = (const float*)d_in[3];  const float* b1 = (const float*)d_in[4];
    const float* g1 = (const float*)d_in[5];  const float* be1 = (const float*)d_in[6];
    const float* W2 = (const float*)d_in[7];  const float* b2 = (const float*)d_in[8];
    const float* g2 = (const float*)d_in[9];  const float* be2 = (const float*)d_in[10];
    const float* W3 = (const float*)d_in[11]; const float* b3 = (const float*)d_in[12];
    const float* g3 = (const float*)d_in[13]; const float* be3 = (const float*)d_in[14];
    const float* Wo = (const float*)d_in[15]; const float* bo = (const float*)d_in[16];
    float* out = (float*)d_out;

    int E = in_sizes[1] / 2;
    const int* row = ei;
    const int* col = ei + E;

    float *h, *agg, *deg, *dinv, *sum, *sqs, *pool, *cnt;
    cudaGetSymbolAddress((void**)&h, g_h);
    cudaGetSymbolAddress((void**)&agg, g_agg);
    cudaGetSymbolAddress((void**)&deg, g_deg);
    cudaGetSymbolAddress((void**)&dinv, g_dinv);
    cudaGetSymbolAddress((void**)&sum, g_sum);
    cudaGetSymbolAddress((void**)&sqs, g_sqs);
    cudaGetSymbolAddress((void**)&pool, g_pool);
    cudaGetSymbolAddress((void**)&cnt, g_cnt);

    // degree (with self loops) -> dinv
    k_fill<<<(NN + 255) / 256, 256>>>(deg, NN, 1.0f);
    k_deg_edges<<<(E + 255) / 256, 256>>>(col, deg, E);
    k_dinv<<<(NN + 255) / 256, 256>>>(deg, dinv, NN);

    // 3 GCN layers (activations live in g_agg between layers)
    run_layer(x,   128, 512, W1, b1, g1, be1, row, col, E, h, agg, dinv, sum, sqs);
    run_layer(agg, 512, 256, W2, b2, g2, be2, row, col, E, h, agg, dinv, sum, sqs);
    run_layer(agg, 256, 128, W3, b3, g3, be3, row, col, E, h, agg, dinv, sum, sqs);

    // global mean pool + head
    k_fill<<<(NG * 128 + 255) / 256, 256>>>(pool, NG * 128, 0.0f);
    k_fill<<<1, 128>>>(cnt, NG, 0.0f);
    k_cnt<<<(NN + 255) / 256, 256>>>(batch, cnt, NN);
    k_poolsum<<<(NN * 128 + 255) / 256, 256>>>(agg, batch, pool, NN * 128);
    k_final<<<(NG * 10 + 127) / 128, 128>>>(pool, cnt, Wo, bo, out);
}

// round 3
// speedup vs baseline: 1.4637x; 1.0807x over previous
#include <cuda_runtime.h>

#define NN 50000
#define NG 64
#define MAXH 512
#define BN_EPS 1e-5f

// ---------------- scratch (device globals; no allocation allowed) -------------
__device__ __align__(16) float g_h[(size_t)NN * MAXH];     // GEMM output (pre-norm h)
__device__ __align__(16) float g_agg[(size_t)NN * MAXH];   // conv output (raw, pre-BN)
__device__ float g_deg[NN];
__device__ float g_dinv[NN];
__device__ float g_sum[MAXH];
__device__ float g_sqs[MAXH];
__device__ __align__(16) float g_scale[MAXH];
__device__ __align__(16) float g_shift[MAXH];
__device__ float g_pool[NG * 128];
__device__ float g_cnt[NG];

// ---------------- small utility kernels --------------------------------------
__global__ void k_fill(float* p, int n, float v) {
    int i = blockIdx.x * blockDim.x + threadIdx.x;
    if (i < n) p[i] = v;
}

__global__ void k_deg_edges(const int* __restrict__ col, float* deg, int E) {
    int i = blockIdx.x * blockDim.x + threadIdx.x;
    if (i < E) atomicAdd(&deg[col[i]], 1.0f);
}

__global__ void k_dinv(const float* __restrict__ deg, float* dinv, int n) {
    int i = blockIdx.x * blockDim.x + threadIdx.x;
    if (i < n) {
        float d = deg[i];
        dinv[i] = d > 0.f ? rsqrtf(d) : 0.f;
    }
}

// BN affine params: scale = g*rsqrt(var+eps), shift = be - mean*scale
__global__ void k_bnparam(const float* __restrict__ sum, const float* __restrict__ sqs,
                          const float* __restrict__ g, const float* __restrict__ be,
                          float* __restrict__ scale, float* __restrict__ shift, int H) {
    int c = blockIdx.x * blockDim.x + threadIdx.x;
    if (c >= H) return;
    const float invN = 1.0f / (float)NN;
    float mean = sum[c] * invN;
    float var = sqs[c] * invN - mean * mean;
    float s = g[c] * rsqrtf(var + BN_EPS);
    scale[c] = s;
    shift[c] = be[c] - mean * s;
}

// ---------------- 128x128x16 double-buffered SGEMM, 8x8 per thread -----------
// C = act(A)[M,K] @ B[K,N], act = BN+ReLU via scaleK/shiftK when BN=true.
// Fused epilogue: H = C ; AGG = C*dinv[row]^2 + bias[col]
#define TBM 128
#define TBN 128
#define TBK 16
#define ASTRIDE 132

template <bool BN>
__global__ __launch_bounds__(256, 2)
void k_gemm_fused(const float* __restrict__ A, const float* __restrict__ B,
                  float* __restrict__ H, float* __restrict__ AGG,
                  const float* __restrict__ dinv, const float* __restrict__ bias,
                  const float* __restrict__ scaleK, const float* __restrict__ shiftK,
                  int M, int K, int N) {
    __shared__ float As[2][TBK][ASTRIDE];
    __shared__ float Bs[2][TBK][TBN];

    const int tid = threadIdx.x;
    const int rowBase = blockIdx.y * TBM;
    const int colBase = blockIdx.x * TBN;

    const int ar = tid >> 2;           // 0..63 (+64)
    const int ac = (tid & 3) << 2;     // 0,4,8,12
    const int br = tid >> 5;           // 0..7 (+8)
    const int bc = (tid & 31) << 2;

    const int tx = tid & 15;
    const int ty = tid >> 4;

    float acc[8][8] = {};
    const int nk = K / TBK;

    // preload tile 0
    {
        float4 sc, sh;
        if (BN) {
            sc = *(const float4*)&scaleK[ac];
            sh = *(const float4*)&shiftK[ac];
        }
#pragma unroll
        for (int s = 0; s < 2; s++) {
            int r = ar + s * 64;
            int gr = rowBase + r;
            float4 v = make_float4(0.f, 0.f, 0.f, 0.f);
            if (gr < M) {
                v = *(const float4*)&A[(size_t)gr * K + ac];
                if (BN) {
                    v.x = fmaxf(v.x * sc.x + sh.x, 0.f);
                    v.y = fmaxf(v.y * sc.y + sh.y, 0.f);
                    v.z = fmaxf(v.z * sc.z + sh.z, 0.f);
                    v.w = fmaxf(v.w * sc.w + sh.w, 0.f);
                }
            }
            As[0][ac + 0][r] = v.x; As[0][ac + 1][r] = v.y;
            As[0][ac + 2][r] = v.z; As[0][ac + 3][r] = v.w;
        }
#pragma unroll
        for (int s = 0; s < 2; s++) {
            int r = br + s * 8;
            *(float4*)&Bs[0][r][bc] = *(const float4*)&B[(size_t)r * N + colBase + bc];
        }
    }
    __syncthreads();

    for (int kt = 0; kt < nk; kt++) {
        int buf = kt & 1;
        if (kt + 1 < nk) {
            int k0 = (kt + 1) * TBK;
            float4 sc, sh;
            if (BN) {
                sc = *(const float4*)&scaleK[k0 + ac];
                sh = *(const float4*)&shiftK[k0 + ac];
            }
#pragma unroll
            for (int s = 0; s < 2; s++) {
                int r = ar + s * 64;
                int gr = rowBase + r;
                float4 v = make_float4(0.f, 0.f, 0.f, 0.f);
                if (gr < M) {
                    v = *(const float4*)&A[(size_t)gr * K + k0 + ac];
                    if (BN) {
                        v.x = fmaxf(v.x * sc.x + sh.x, 0.f);
                        v.y = fmaxf(v.y * sc.y + sh.y, 0.f);
                        v.z = fmaxf(v.z * sc.z + sh.z, 0.f);
                        v.w = fmaxf(v.w * sc.w + sh.w, 0.f);
                    }
                }
                As[buf ^ 1][ac + 0][r] = v.x; As[buf ^ 1][ac + 1][r] = v.y;
                As[buf ^ 1][ac + 2][r] = v.z; As[buf ^ 1][ac + 3][r] = v.w;
            }
#pragma unroll
            for (int s = 0; s < 2; s++) {
                int r = br + s * 8;
                *(float4*)&Bs[buf ^ 1][r][bc] =
                    *(const float4*)&B[(size_t)(k0 + r) * N + colBase + bc];
            }
        }

#pragma unroll
        for (int k = 0; k < TBK; k++) {
            float a[8], b[8];
            *(float4*)&a[0] = *(const float4*)&As[buf][k][ty * 4];
            *(float4*)&a[4] = *(const float4*)&As[buf][k][ty * 4 + 64];
            *(float4*)&b[0] = *(const float4*)&Bs[buf][k][tx * 4];
            *(float4*)&b[4] = *(const float4*)&Bs[buf][k][tx * 4 + 64];
#pragma unroll
            for (int i = 0; i < 8; i++)
#pragma unroll
                for (int j = 0; j < 8; j++)
                    acc[i][j] += a[i] * b[j];
        }
        __syncthreads();
    }

    float4 bl0 = *(const float4*)&bias[colBase + tx * 4];
    float4 bl1 = *(const float4*)&bias[colBase + tx * 4 + 64];
    float blo[8] = {bl0.x, bl0.y, bl0.z, bl0.w, bl1.x, bl1.y, bl1.z, bl1.w};

#pragma unroll
    for (int i = 0; i < 8; i++) {
        int r = (i < 4) ? (ty * 4 + i) : (ty * 4 + 64 + i - 4);
        int gr = rowBase + r;
        if (gr >= M) continue;
        float di = dinv[gr];
        float d2 = di * di;
        size_t base = (size_t)gr * N;
#pragma unroll
        for (int jj = 0; jj < 2; jj++) {
            int c = colBase + tx * 4 + jj * 64;
            float4 hv = make_float4(acc[i][jj * 4 + 0], acc[i][jj * 4 + 1],
                                    acc[i][jj * 4 + 2], acc[i][jj * 4 + 3]);
            *(float4*)&H[base + c] = hv;
            float4 av = make_float4(hv.x * d2 + blo[jj * 4 + 0],
                                    hv.y * d2 + blo[jj * 4 + 1],
                                    hv.z * d2 + blo[jj * 4 + 2],
                                    hv.w * d2 + blo[jj * 4 + 3]);
            *(float4*)&AGG[base + c] = av;
        }
    }
}

// ---------------- edge scatter: agg[col] += h[row] * dinv[row]*dinv[col] ------
__global__ void k_scatter(const float* __restrict__ h, const int* __restrict__ row,
                          const int* __restrict__ col, const float* __restrict__ dinv,
                          float* __restrict__ agg, int items, int cshift, int H) {
    int i = blockIdx.x * blockDim.x + threadIdx.x;
    if (i >= items) return;
    int e = i >> cshift;
    int c = (i - (e << cshift)) << 2;
    int r = __ldg(&row[e]);
    int d = __ldg(&col[e]);
    float nrm = __ldg(&dinv[r]) * __ldg(&dinv[d]);
    float4 v = __ldg((const float4*)(h + (size_t)r * H + c));
    float wx = v.x * nrm, wy = v.y * nrm, wz = v.z * nrm, ww = v.w * nrm;
    float* dst = agg + (size_t)d * H + c;
    asm volatile("red.global.add.v4.f32 [%0], {%1,%2,%3,%4};"
                 :: "l"(dst), "f"(wx), "f"(wy), "f"(wz), "f"(ww) : "memory");
}

// ---------------- BN statistics: register-accumulating, coalesced -------------
__global__ void k_zero2(float* a, float* b, int n) {
    int i = blockIdx.x * blockDim.x + threadIdx.x;
    if (i < n) { a[i] = 0.f; b[i] = 0.f; }
}

__global__ void k_stats(const float* __restrict__ x, int rows, int H,
                        float* __restrict__ sum, float* __restrict__ sqs) {
    int c = blockIdx.x * blockDim.x + threadIdx.x;   // feature column
    if (c >= H) return;
    float s = 0.f, q = 0.f;
    for (int r = blockIdx.y; r < rows; r += gridDim.y) {
        float v = x[(size_t)r * H + c];
        s += v;
        q += v * v;
    }
    atomicAdd(&sum[c], s);
    atomicAdd(&sqs[c], q);
}

// ---------------- pooling (fused BN+ReLU) + output head -----------------------
__global__ void k_cnt(const int* __restrict__ batch, float* cnt, int n) {
    int i = blockIdx.x * blockDim.x + threadIdx.x;
    if (i < n) atomicAdd(&cnt[batch[i]], 1.0f);
}

__global__ void k_poolsum_bn(const float* __restrict__ agg, const int* __restrict__ batch,
                             const float* __restrict__ scale, const float* __restrict__ shift,
                             float* __restrict__ pool, int total) {
    int i = blockIdx.x * blockDim.x + threadIdx.x;
    if (i >= total) return;
    int node = i >> 7;          // H3 = 128
    int c = i & 127;
    float v = fmaxf(agg[i] * scale[c] + shift[c], 0.f);
    atomicAdd(&pool[batch[node] * 128 + c], v);
}

__global__ void k_final(const float* __restrict__ pool, const float* __restrict__ cnt,
                        const float* __restrict__ Wo, const float* __restrict__ bo,
                        float* __restrict__ out) {
    int t = blockIdx.x * blockDim.x + threadIdx.x;
    if (t >= NG * 10) return;
    int gph = t / 10, o = t % 10;
    float inv = 1.0f / fmaxf(cnt[gph], 1.0f);
    float acc = bo[o];
#pragma unroll 8
    for (int k = 0; k < 128; k++)
        acc += pool[gph * 128 + k] * inv * Wo[k * 10 + o];
    out[t] = acc;
}

// ---------------- host orchestration ------------------------------------------
static inline int ilog2(int v) { int s = 0; while ((1 << s) < v) s++; return s; }

struct Ptrs {
    float *h, *agg, *deg, *dinv, *sum, *sqs, *scale, *shift, *pool, *cnt;
};

static void run_layer(const float* in, int K, int H, const float* W, const float* b,
                      const int* row, const int* col, int E, const Ptrs& p, bool bn) {
    dim3 grid(H / TBN, (NN + TBM - 1) / TBM);
    if (bn)
        k_gemm_fused<true><<<grid, 256>>>(in, W, p.h, p.agg, p.dinv, b,
                                          p.scale, p.shift, NN, K, H);
    else
        k_gemm_fused<false><<<grid, 256>>>(in, W, p.h, p.agg, p.dinv, b,
                                           nullptr, nullptr, NN, K, H);

    int cshift = ilog2(H / 4);
    int items = E * (H / 4);
    k_scatter<<<(items + 255) / 256, 256>>>(p.h, row, col, p.dinv, p.agg, items, cshift, H);

    k_zero2<<<(H + 127) / 128, 128>>>(p.sum, p.sqs, H);
    dim3 sgrid((H + 255) / 256, 512);
    k_stats<<<sgrid, 256>>>(p.agg, NN, H, p.sum, p.sqs);
}

extern "C" void kernel_launch(void* const* d_in, const int* in_sizes, int n_in,
                              void* d_out, int out_size) {
    const float* x     = (const float*)d_in[0];
    const int*   ei    = (const int*)d_in[1];
    const int*   batch = (const int*)d_in[2];
    const float* W1 = (const float*)d_in[3];  const float* b1 = (const float*)d_in[4];
    const float* g1 = (const float*)d_in[5];  const float* be1 = (const float*)d_in[6];
    const float* W2 = (const float*)d_in[7];  const float* b2 = (const float*)d_in[8];
    const float* g2 = (const float*)d_in[9];  const float* be2 = (const float*)d_in[10];
    const float* W3 = (const float*)d_in[11]; const float* b3 = (const float*)d_in[12];
    const float* g3 = (const float*)d_in[13]; const float* be3 = (const float*)d_in[14];
    const float* Wo = (const float*)d_in[15]; const float* bo = (const float*)d_in[16];
    float* out = (float*)d_out;

    int E = in_sizes[1] / 2;
    const int* row = ei;
    const int* col = ei + E;

    Ptrs p;
    cudaGetSymbolAddress((void**)&p.h, g_h);
    cudaGetSymbolAddress((void**)&p.agg, g_agg);
    cudaGetSymbolAddress((void**)&p.deg, g_deg);
    cudaGetSymbolAddress((void**)&p.dinv, g_dinv);
    cudaGetSymbolAddress((void**)&p.sum, g_sum);
    cudaGetSymbolAddress((void**)&p.sqs, g_sqs);
    cudaGetSymbolAddress((void**)&p.scale, g_scale);
    cudaGetSymbolAddress((void**)&p.shift, g_shift);
    cudaGetSymbolAddress((void**)&p.pool, g_pool);
    cudaGetSymbolAddress((void**)&p.cnt, g_cnt);

    // degree (with self loops) -> dinv
    k_fill<<<(NN + 255) / 256, 256>>>(p.deg, NN, 1.0f);
    k_deg_edges<<<(E + 255) / 256, 256>>>(col, p.deg, E);
    k_dinv<<<(NN + 255) / 256, 256>>>(p.deg, p.dinv, NN);

    // layer 1: raw x input
    run_layer(x, 128, 512, W1, b1, row, col, E, p, false);

    // layer 2: BN+ReLU of agg fused into GEMM A-load
    k_bnparam<<<(512 + 127) / 128, 128>>>(p.sum, p.sqs, g1, be1, p.scale, p.shift, 512);
    run_layer(p.agg, 512, 256, W2, b2, row, col, E, p, true);

    // layer 3
    k_bnparam<<<(256 + 127) / 128, 128>>>(p.sum, p.sqs, g2, be2, p.scale, p.shift, 256);
    run_layer(p.agg, 256, 128, W3, b3, row, col, E, p, true);

    // final BN params + pool (BN+ReLU fused) + head
    k_bnparam<<<1, 128>>>(p.sum, p.sqs, g3, be3, p.scale, p.shift, 128);
    k_fill<<<(NG * 128 + 255) / 256, 256>>>(p.pool, NG * 128, 0.0f);
    k_fill<<<1, 128>>>(p.cnt, NG, 0.0f);
    k_cnt<<<(NN + 255) / 256, 256>>>(batch, p.cnt, NN);
    k_poolsum_bn<<<(NN * 128 + 255) / 256, 256>>>(p.agg, batch, p.scale, p.shift,
                                                  p.pool, NN * 128);
    k_final<<<(NG * 10 + 127) / 128, 128>>>(p.pool, p.cnt, Wo, bo, out);
}

// round 4
// speedup vs baseline: 2.2428x; 1.5323x over previous
#include <cuda_runtime.h>

#define NN 50000
#define NG 64
#define MAXE 800000
#define MAXH 512
#define BN_EPS 1e-5f
#define SCAN_B 1024

// ---------------- scratch (device globals) ------------------------------------
__device__ __align__(16) float g_h[(size_t)NN * MAXH];
__device__ __align__(16) float g_agg[(size_t)NN * MAXH];
__device__ float g_dinv[NN];
__device__ int   g_cnt[NN];
__device__ int   g_cursor[NN];
__device__ int   g_off[NN + 1];
__device__ int   g_bsum[64];
__device__ int   g_csrc[MAXE];
__device__ float g_cw[MAXE];
__device__ float g_sum[MAXH];
__device__ float g_sqs[MAXH];
__device__ __align__(16) float g_mean[MAXH];
__device__ __align__(16) float g_scale[MAXH];
__device__ int   g_gstart[NG + 1];

// ---------------- CSR build ----------------------------------------------------
__global__ void k_zeroi(int* p, int n) {
    int i = blockIdx.x * blockDim.x + threadIdx.x;
    if (i < n) p[i] = 0;
}

__global__ void k_count(const int* __restrict__ col, int* cnt, int E) {
    int i = blockIdx.x * blockDim.x + threadIdx.x;
    if (i < E) atomicAdd(&cnt[col[i]], 1);
}

__global__ void k_scan1(const int* __restrict__ cnt, int* off, int* bsum, int n) {
    __shared__ int sh[SCAN_B];
    int i = blockIdx.x * SCAN_B + threadIdx.x;
    sh[threadIdx.x] = (i < n) ? cnt[i] : 0;
    __syncthreads();
#pragma unroll
    for (int d = 1; d < SCAN_B; d <<= 1) {
        int t = (threadIdx.x >= d) ? sh[threadIdx.x - d] : 0;
        __syncthreads();
        sh[threadIdx.x] += t;
        __syncthreads();
    }
    if (i < n) off[i + 1] = sh[threadIdx.x];
    if (threadIdx.x == SCAN_B - 1) bsum[blockIdx.x] = sh[SCAN_B - 1];
}

__global__ void k_scan2(int* bsum, int nb, int* off) {
    if (threadIdx.x == 0) {
        off[0] = 0;
        int s = 0;
        for (int b = 0; b < nb; b++) { s += bsum[b]; bsum[b] = s; }
    }
}

__global__ void k_scan3(int* off, const int* __restrict__ bsum, int n) {
    int b = blockIdx.x + 1;
    int i = b * SCAN_B + threadIdx.x;
    if (i < n) off[i + 1] += bsum[b - 1];
}

__global__ void k_dinv2(const int* __restrict__ cnt, float* dinv, int n) {
    int i = blockIdx.x * blockDim.x + threadIdx.x;
    if (i < n) dinv[i] = rsqrtf((float)(cnt[i] + 1));   // +1 self loop, always > 0
}

__global__ void k_place(const int* __restrict__ row, const int* __restrict__ col,
                        const float* __restrict__ dinv, const int* __restrict__ off,
                        int* cursor, int* csrc, float* cw, int E) {
    int e = blockIdx.x * blockDim.x + threadIdx.x;
    if (e >= E) return;
    int d = col[e], r = row[e];
    int pos = off[d] + atomicAdd(&cursor[d], 1);
    csrc[pos] = r;
    cw[pos] = dinv[r] * dinv[d];
}

// ---------------- BN params -----------------------------------------------------
__global__ void k_bnparam(const float* __restrict__ sum, const float* __restrict__ sqs,
                          const float* __restrict__ g, float* __restrict__ mean,
                          float* __restrict__ scale, int H) {
    int c = blockIdx.x * blockDim.x + threadIdx.x;
    if (c >= H) return;
    const float invN = 1.0f / (float)NN;
    float m = sum[c] * invN;
    float var = sqs[c] * invN - m * m;
    mean[c] = m;
    scale[c] = g[c] * rsqrtf(var + BN_EPS);
}

// ---------------- 128x128x16 double-buffered SGEMM, 8x8 per thread -------------
// C = act(A) @ B, act = BN((x-mean)*scale + be) + ReLU when BN=true.
// Epilogue: H = C ; AGG = C*dinv[row]^2 + bias[col]
#define TBM 128
#define TBN 128
#define TBK 16
#define ASTRIDE 132

template <bool BN>
__global__ __launch_bounds__(256, 2)
void k_gemm_fused(const float* __restrict__ A, const float* __restrict__ B,
                  float* __restrict__ H, float* __restrict__ AGG,
                  const float* __restrict__ dinv, const float* __restrict__ bias,
                  const float* __restrict__ meanK, const float* __restrict__ scaleK,
                  const float* __restrict__ beK,
                  int M, int K, int N) {
    __shared__ float As[2][TBK][ASTRIDE];
    __shared__ float Bs[2][TBK][TBN];

    const int tid = threadIdx.x;
    const int rowBase = blockIdx.y * TBM;
    const int colBase = blockIdx.x * TBN;

    const int ar = tid >> 2;
    const int ac = (tid & 3) << 2;
    const int br = tid >> 5;
    const int bc = (tid & 31) << 2;
    const int tx = tid & 15;
    const int ty = tid >> 4;

    float acc[8][8] = {};
    const int nk = K / TBK;

    // preload tile 0
    {
        float4 mn, sc, be;
        if (BN) {
            mn = *(const float4*)&meanK[ac];
            sc = *(const float4*)&scaleK[ac];
            be = *(const float4*)&beK[ac];
        }
#pragma unroll
        for (int s = 0; s < 2; s++) {
            int r = ar + s * 64;
            int gr = rowBase + r;
            float4 v = make_float4(0.f, 0.f, 0.f, 0.f);
            if (gr < M) {
                v = *(const float4*)&A[(size_t)gr * K + ac];
                if (BN) {
                    v.x = fmaxf((v.x - mn.x) * sc.x + be.x, 0.f);
                    v.y = fmaxf((v.y - mn.y) * sc.y + be.y, 0.f);
                    v.z = fmaxf((v.z - mn.z) * sc.z + be.z, 0.f);
                    v.w = fmaxf((v.w - mn.w) * sc.w + be.w, 0.f);
                }
            }
            As[0][ac + 0][r] = v.x; As[0][ac + 1][r] = v.y;
            As[0][ac + 2][r] = v.z; As[0][ac + 3][r] = v.w;
        }
#pragma unroll
        for (int s = 0; s < 2; s++) {
            int r = br + s * 8;
            *(float4*)&Bs[0][r][bc] = *(const float4*)&B[(size_t)r * N + colBase + bc];
        }
    }
    __syncthreads();

    for (int kt = 0; kt < nk; kt++) {
        int buf = kt & 1;
        if (kt + 1 < nk) {
            int k0 = (kt + 1) * TBK;
            float4 mn, sc, be;
            if (BN) {
                mn = *(const float4*)&meanK[k0 + ac];
                sc = *(const float4*)&scaleK[k0 + ac];
                be = *(const float4*)&beK[k0 + ac];
            }
#pragma unroll
            for (int s = 0; s < 2; s++) {
                int r = ar + s * 64;
                int gr = rowBase + r;
                float4 v = make_float4(0.f, 0.f, 0.f, 0.f);
                if (gr < M) {
                    v = *(const float4*)&A[(size_t)gr * K + k0 + ac];
                    if (BN) {
                        v.x = fmaxf((v.x - mn.x) * sc.x + be.x, 0.f);
                        v.y = fmaxf((v.y - mn.y) * sc.y + be.y, 0.f);
                        v.z = fmaxf((v.z - mn.z) * sc.z + be.z, 0.f);
                        v.w = fmaxf((v.w - mn.w) * sc.w + be.w, 0.f);
                    }
                }
                As[buf ^ 1][ac + 0][r] = v.x; As[buf ^ 1][ac + 1][r] = v.y;
                As[buf ^ 1][ac + 2][r] = v.z; As[buf ^ 1][ac + 3][r] = v.w;
            }
#pragma unroll
            for (int s = 0; s < 2; s++) {
                int r = br + s * 8;
                *(float4*)&Bs[buf ^ 1][r][bc] =
                    *(const float4*)&B[(size_t)(k0 + r) * N + colBase + bc];
            }
        }

#pragma unroll
        for (int k = 0; k < TBK; k++) {
            float a[8], b[8];
            *(float4*)&a[0] = *(const float4*)&As[buf][k][ty * 4];
            *(float4*)&a[4] = *(const float4*)&As[buf][k][ty * 4 + 64];
            *(float4*)&b[0] = *(const float4*)&Bs[buf][k][tx * 4];
            *(float4*)&b[4] = *(const float4*)&Bs[buf][k][tx * 4 + 64];
#pragma unroll
            for (int i = 0; i < 8; i++)
#pragma unroll
                for (int j = 0; j < 8; j++)
                    acc[i][j] += a[i] * b[j];
        }
        __syncthreads();
    }

    float4 bl0 = *(const float4*)&bias[colBase + tx * 4];
    float4 bl1 = *(const float4*)&bias[colBase + tx * 4 + 64];
    float blo[8] = {bl0.x, bl0.y, bl0.z, bl0.w, bl1.x, bl1.y, bl1.z, bl1.w};

#pragma unroll
    for (int i = 0; i < 8; i++) {
        int r = (i < 4) ? (ty * 4 + i) : (ty * 4 + 64 + i - 4);
        int gr = rowBase + r;
        if (gr >= M) continue;
        float di = dinv[gr];
        float d2 = di * di;
        size_t base = (size_t)gr * N;
#pragma unroll
        for (int jj = 0; jj < 2; jj++) {
            int c = colBase + tx * 4 + jj * 64;
            float4 hv = make_float4(acc[i][jj * 4 + 0], acc[i][jj * 4 + 1],
                                    acc[i][jj * 4 + 2], acc[i][jj * 4 + 3]);
            *(float4*)&H[base + c] = hv;
            float4 av = make_float4(hv.x * d2 + blo[jj * 4 + 0],
                                    hv.y * d2 + blo[jj * 4 + 1],
                                    hv.z * d2 + blo[jj * 4 + 2],
                                    hv.w * d2 + blo[jj * 4 + 3]);
            *(float4*)&AGG[base + c] = av;
        }
    }
}

// ---------------- CSR gather: agg[n] += sum_e w[e] * h[src[e]] -----------------
// block = 128 threads; nodes per block = 512/H; tpn = H/4 threads per node.
__global__ void k_gather(const float* __restrict__ h, const int* __restrict__ csrc,
                         const float* __restrict__ cw, const int* __restrict__ off,
                         float* __restrict__ agg, int H, int tpnshift) {
    int tpn = 1 << tpnshift;
    int local = threadIdx.x >> tpnshift;
    int node = blockIdx.x * (blockDim.x >> tpnshift) + local;
    if (node >= NN) return;
    int c = (threadIdx.x & (tpn - 1)) << 2;
    int s = __ldg(&off[node]);
    int e = __ldg(&off[node + 1]);
    float ax = 0.f, ay = 0.f, az = 0.f, aw = 0.f;
    for (int i = s; i < e; i++) {
        int src = __ldg(&csrc[i]);
        float w = __ldg(&cw[i]);
        float4 v = __ldg((const float4*)(h + (size_t)src * H + c));
        ax += v.x * w; ay += v.y * w; az += v.z * w; aw += v.w * w;
    }
    float4 cur = *(float4*)&agg[(size_t)node * H + c];
    cur.x += ax; cur.y += ay; cur.z += az; cur.w += aw;
    *(float4*)&agg[(size_t)node * H + c] = cur;
}

// ---------------- BN statistics --------------------------------------------------
__global__ void k_zero2(float* a, float* b, int n) {
    int i = blockIdx.x * blockDim.x + threadIdx.x;
    if (i < n) { a[i] = 0.f; b[i] = 0.f; }
}

__global__ void k_stats(const float* __restrict__ x, int rows, int H,
                        float* __restrict__ sum, float* __restrict__ sqs) {
    int c = blockIdx.x * blockDim.x + threadIdx.x;
    if (c >= H) return;
    float s = 0.f, q = 0.f;
    for (int r = blockIdx.y; r < rows; r += gridDim.y) {
        float v = x[(size_t)r * H + c];
        s += v;
        q += v * v;
    }
    atomicAdd(&sum[c], s);
    atomicAdd(&sqs[c], q);
}

// ---------------- graph boundaries (batch is sorted) ----------------------------
__global__ void k_bounds(const int* __restrict__ batch, int* gstart, int n) {
    int i = blockIdx.x * blockDim.x + threadIdx.x;
    if (i >= n) return;
    int bi = batch[i];
    int bp = (i == 0) ? -1 : batch[i - 1];
    for (int g = bp + 1; g <= bi; g++) gstart[g] = i;
    if (i == n - 1)
        for (int g = bi + 1; g <= NG; g++) gstart[g] = n;
}

// ---------------- fused BN+ReLU + mean-pool + head (one block per graph) --------
__global__ void k_pool_head(const float* __restrict__ agg, const int* __restrict__ gstart,
                            const float* __restrict__ mean, const float* __restrict__ scale,
                            const float* __restrict__ be, const float* __restrict__ Wo,
                            const float* __restrict__ bo, float* __restrict__ out) {
    __shared__ float pooled[128];
    int g = blockIdx.x;
    int c = threadIdx.x;               // 128 threads, H3 = 128
    int s = gstart[g], e = gstart[g + 1];
    float mn = mean[c], sc = scale[c], bb = be[c];
    float acc = 0.f;
    for (int n = s; n < e; n++)
        acc += fmaxf((agg[(size_t)n * 128 + c] - mn) * sc + bb, 0.f);
    float inv = 1.0f / (float)max(e - s, 1);
    pooled[c] = acc * inv;
    __syncthreads();
    if (c < 10) {
        float o = bo[c];
#pragma unroll 8
        for (int k = 0; k < 128; k++)
            o += pooled[k] * Wo[k * 10 + c];
        out[g * 10 + c] = o;
    }
}

// ---------------- host orchestration --------------------------------------------
static inline int ilog2(int v) { int s = 0; while ((1 << s) < v) s++; return s; }

struct Ptrs {
    float *h, *agg, *dinv, *sum, *sqs, *mean, *scale, *cw;
    int *cnt, *cursor, *off, *bsum, *csrc, *gstart;
};

static void run_layer(const float* in, int K, int H, const float* W, const float* b,
                      const float* meanK, const float* scaleK, const float* beK,
                      const Ptrs& p) {
    dim3 grid(H / TBN, (NN + TBM - 1) / TBM);
    if (meanK)
        k_gemm_fused<true><<<grid, 256>>>(in, W, p.h, p.agg, p.dinv, b,
                                          meanK, scaleK, beK, NN, K, H);
    else
        k_gemm_fused<false><<<grid, 256>>>(in, W, p.h, p.agg, p.dinv, b,
                                           nullptr, nullptr, nullptr, NN, K, H);

    int tpnshift = ilog2(H / 4);
    int npb = 128 >> tpnshift;
    k_gather<<<(NN + npb - 1) / npb, 128>>>(p.h, p.csrc, p.cw, p.off, p.agg, H, tpnshift);

    k_zero2<<<(H + 127) / 128, 128>>>(p.sum, p.sqs, H);
    dim3 sgrid((H + 255) / 256, 512);
    k_stats<<<sgrid, 256>>>(p.agg, NN, H, p.sum, p.sqs);
}

extern "C" void kernel_launch(void* const* d_in, const int* in_sizes, int n_in,
                              void* d_out, int out_size) {
    const float* x     = (const float*)d_in[0];
    const int*   ei    = (const int*)d_in[1];
    const int*   batch = (const int*)d_in[2];
    const float* W1 = (const float*)d_in[3];  const float* b1 = (const float*)d_in[4];
    const float* g1 = (const float*)d_in[5];  const float* be1 = (const float*)d_in[6];
    const float* W2 = (const float*)d_in[7];  const float* b2 = (const float*)d_in[8];
    const float* g2 = (const float*)d_in[9];  const float* be2 = (const float*)d_in[10];
    const float* W3 = (const float*)d_in[11]; const float* b3 = (const float*)d_in[12];
    const float* g3 = (const float*)d_in[13]; const float* be3 = (const float*)d_in[14];
    const float* Wo = (const float*)d_in[15]; const float* bo = (const float*)d_in[16];
    float* out = (float*)d_out;

    int E = in_sizes[1] / 2;
    const int* row = ei;
    const int* col = ei + E;

    Ptrs p;
    cudaGetSymbolAddress((void**)&p.h, g_h);
    cudaGetSymbolAddress((void**)&p.agg, g_agg);
    cudaGetSymbolAddress((void**)&p.dinv, g_dinv);
    cudaGetSymbolAddress((void**)&p.sum, g_sum);
    cudaGetSymbolAddress((void**)&p.sqs, g_sqs);
    cudaGetSymbolAddress((void**)&p.mean, g_mean);
    cudaGetSymbolAddress((void**)&p.scale, g_scale);
    cudaGetSymbolAddress((void**)&p.cw, g_cw);
    cudaGetSymbolAddress((void**)&p.cnt, g_cnt);
    cudaGetSymbolAddress((void**)&p.cursor, g_cursor);
    cudaGetSymbolAddress((void**)&p.off, g_off);
    cudaGetSymbolAddress((void**)&p.bsum, g_bsum);
    cudaGetSymbolAddress((void**)&p.csrc, g_csrc);
    cudaGetSymbolAddress((void**)&p.gstart, g_gstart);

    // ---- build CSR (dst-grouped) + dinv ----
    int nb = (NN + SCAN_B - 1) / SCAN_B;
    k_zeroi<<<(NN + 255) / 256, 256>>>(p.cnt, NN);
    k_count<<<(E + 255) / 256, 256>>>(col, p.cnt, E);
    k_scan1<<<nb, SCAN_B>>>(p.cnt, p.off, p.bsum, NN);
    k_scan2<<<1, 32>>>(p.bsum, nb, p.off);
    if (nb > 1) k_scan3<<<nb - 1, SCAN_B>>>(p.off, p.bsum, NN);
    k_dinv2<<<(NN + 255) / 256, 256>>>(p.cnt, p.dinv, NN);
    k_zeroi<<<(NN + 255) / 256, 256>>>(p.cursor, NN);
    k_place<<<(E + 255) / 256, 256>>>(row, col, p.dinv, p.off, p.cursor,
                                      p.csrc, p.cw, E);

    // graph boundaries for pooling
    k_bounds<<<(NN + 255) / 256, 256>>>(batch, p.gstart, NN);

    // ---- 3 GCN layers ----
    run_layer(x, 128, 512, W1, b1, nullptr, nullptr, nullptr, p);

    k_bnparam<<<(512 + 127) / 128, 128>>>(p.sum, p.sqs, g1, p.mean, p.scale, 512);
    run_layer(p.agg, 512, 256, W2, b2, p.mean, p.scale, be1, p);

    k_bnparam<<<(256 + 127) / 128, 128>>>(p.sum, p.sqs, g2, p.mean, p.scale, 256);
    run_layer(p.agg, 256, 128, W3, b3, p.mean, p.scale, be2, p);

    // ---- final BN + pool + head ----
    k_bnparam<<<1, 128>>>(p.sum, p.sqs, g3, p.mean, p.scale, 128);
    k_pool_head<<<NG, 128>>>(p.agg, p.gstart, p.mean, p.scale, be3, Wo, bo, out);
}